// round 4
// baseline (speedup 1.0000x reference)
#include <cuda_runtime.h>
#include <cuda_bf16.h>
#include <mma.h>
#include <math.h>

using namespace nvcuda;

#define Nn 50000
#define NR 50048
#define Ee 800000
#define Dd 32
#define NL 6
#define KK 160
#define CN 96
#define BM 128
#define A_LD 40
#define B_LD 104
#define GEMM_SMEM ((2*KK*B_LD + 2*BM*A_LD) * 2)

// ---------------- device scratch ----------------
__device__ float g_h0[Nn * Dd];
__device__ float g_h1[Nn * Dd];
__device__ __nv_bfloat16 g_Xh[NR * KK];
__device__ __nv_bfloat16 g_Xl[NR * KK];
__device__ __nv_bfloat16 g_Wbh[NL * KK * CN];
__device__ __nv_bfloat16 g_Wbl[NL * KK * CN];
__device__ float g_scale[Nn];
__device__ float g_deg[Nn];
__device__ int   g_indeg[Nn];
__device__ int   g_start[Nn];
__device__ int   g_cursor[Nn];
__device__ int2  g_csr[Ee];
__device__ float g_rel[NL * Dd];
__device__ float g_D[Nn];
__device__ float g_sum;
__device__ int   g_tot;
__device__ int   g_pred[Nn];

__device__ __forceinline__ float* hbuf(int s) { return s ? g_h1 : g_h0; }

// ---------------- init: boundary, counters, rel, Wc build ----------------
__global__ void k_init(const int* __restrict__ hptr, const float* __restrict__ q,
                       const float* __restrict__ relW, const float* __restrict__ relb,
                       const float* __restrict__ linW) {
    int idx = blockIdx.x * blockDim.x + threadIdx.x;
    if (idx < Nn * Dd) {
        int n = idx >> 5;
        int h = *hptr;
        g_h0[idx] = (n == h) ? 0.0f : 100.0f;
        if ((idx & 31) == 0) {
            g_deg[n] = 1.0f;
            g_indeg[n] = 0;
        }
    }
    if (idx < NL * KK * CN) {
        int l = idx / (KK * CN);
        int rem = idx % (KK * CN);
        int k = rem / CN;
        int j = rem % CN;
        float v;
        if (k < 32) {
            v = (j < 32) ? linW[(l * 416 + k) * 32 + j] : 0.0f;
        } else {
            int f = k - 32, g = j >> 5, d = j & 31;
            v = linW[(l * 416 + 32 + f * 3 + g) * 32 + d];
        }
        __nv_bfloat16 hh = __float2bfloat16_rn(v);
        g_Wbh[idx] = hh;
        g_Wbl[idx] = __float2bfloat16_rn(v - __bfloat162float(hh));
    }
    if (idx < NL * Dd) {
        int i = idx >> 5, d = idx & 31;
        float acc = relb[i * Dd + d];
        for (int k = 0; k < Dd; k++)
            acc += q[k] * relW[(i * Dd + k) * Dd + d];
        g_rel[i * Dd + d] = acc;
    }
    if (idx == 0) { g_sum = 0.0f; g_tot = 0; }
}

// ---------------- edge counting ----------------
__global__ void k_count(const int* __restrict__ node_out, const float* __restrict__ ew) {
    int e = blockIdx.x * blockDim.x + threadIdx.x;
    if (e >= Ee) return;
    int o = node_out[e];
    atomicAdd(&g_deg[o], ew[e]);
    atomicAdd(&g_indeg[o], 1);
}

// ---------------- segment allocation + log(deg) partial sum ----------------
__global__ void k_alloc() {
    int i = blockIdx.x * blockDim.x + threadIdx.x;
    float s = 0.0f;
    if (i < Nn) {
        int c = g_indeg[i];
        int st = atomicAdd(&g_tot, c);
        g_start[i] = st;
        g_cursor[i] = st;
        s = logf(g_deg[i]);
        g_scale[i] = s;
    }
    for (int o = 16; o; o >>= 1) s += __shfl_xor_sync(0xffffffffu, s, o);
    __shared__ float wsum[8];
    int lane = threadIdx.x & 31, wid = threadIdx.x >> 5;
    if (lane == 0) wsum[wid] = s;
    __syncthreads();
    if (threadIdx.x == 0) {
        float t = 0.0f;
        for (int w = 0; w < 8; w++) t += wsum[w];
        atomicAdd(&g_sum, t);
    }
}

// ---------------- CSR scatter + scale normalize ----------------
__global__ void k_scatter(const int* __restrict__ node_out, const int* __restrict__ node_in,
                          const float* __restrict__ ew) {
    int e = blockIdx.x * blockDim.x + threadIdx.x;
    if (e < Nn) g_scale[e] = g_scale[e] * ((float)Nn / g_sum);
    if (e >= Ee) return;
    int n = node_out[e];
    int p = atomicAdd(&g_cursor[n], 1);
    g_csr[p] = make_int2(node_in[e], __float_as_int(ew[e]));
}

// ---------------- per-node dot(h, rel) ----------------
__global__ void k_dot(int insel, int layer) {
    int warp = (blockIdx.x * blockDim.x + threadIdx.x) >> 5;
    int lane = threadIdx.x & 31;
    if (warp >= Nn) return;
    const float* __restrict__ hin = hbuf(insel);
    float v = hin[warp * Dd + lane] * g_rel[layer * Dd + lane];
    #pragma unroll
    for (int o = 16; o; o >>= 1) v += __shfl_xor_sync(0xffffffffu, v, o);
    if (lane == 0) g_D[warp] = v;
}

// ---------------- aggregation: warp/node, 4 edges per iter, float4 lanes ------
// lane = q*8 + r: quarter q handles edge j+q, r handles dims 4r..4r+3.
template <int LAST>
__global__ void k_agg(const int* __restrict__ hptr, int insel, int layer) {
    int warp = (blockIdx.x * blockDim.x + threadIdx.x) >> 5;
    int lane = threadIdx.x & 31;
    if (warp >= Nn) return;
    int n = warp;
    const float* __restrict__ hin = hbuf(insel);
    int h = *hptr;
    int q = lane >> 3;
    int r = lane & 7;
    const float INF = __int_as_float(0x7f800000);

    float4 relv = *reinterpret_cast<const float4*>(&g_rel[layer * Dd + 4 * r]);

    float b = (n == h) ? 0.0f : 100.0f;
    float4 sum, sq, mx, mn;
    float bestS; int bestSrc;
    if (q == 0) {
        sum = make_float4(b, b, b, b);
        sq  = make_float4(b * b, b * b, b * b, b * b);
        mx  = make_float4(b, b, b, b);
        mn  = mx;
        bestS = 32.0f * b; bestSrc = n;
    } else {
        sum = make_float4(0, 0, 0, 0);
        sq  = make_float4(0, 0, 0, 0);
        mx  = make_float4(-INF, -INF, -INF, -INF);
        mn  = make_float4(INF, INF, INF, INF);
        bestS = -INF; bestSrc = 0x7fffffff;
    }

    int st = g_start[n];
    int cnt = g_indeg[n];
    for (int base = 0; base < cnt; base += 32) {
        int m = cnt - base; if (m > 32) m = 32;
        int2 ed = make_int2(0, 0);
        if (lane < m) ed = g_csr[st + base + lane];

        #pragma unroll 2
        for (int j = 0; j < m; j += 4) {
            int idx = j + q;
            bool valid = idx < m;
            int sel = valid ? idx : j;
            int src = __shfl_sync(0xffffffffu, ed.x, sel);
            float w = __int_as_float(__shfl_sync(0xffffffffu, ed.y, sel));
            float4 v = *reinterpret_cast<const float4*>(&hin[src * Dd + 4 * r]);
            float Dv = 0.0f;
            if (LAST) Dv = g_D[src];
            if (valid) {
                float4 mv, wm;
                mv.x = v.x * relv.x; mv.y = v.y * relv.y;
                mv.z = v.z * relv.z; mv.w = v.w * relv.w;
                wm.x = mv.x * w; wm.y = mv.y * w; wm.z = mv.z * w; wm.w = mv.w * w;
                sum.x += wm.x; sum.y += wm.y; sum.z += wm.z; sum.w += wm.w;
                sq.x += mv.x * mv.x * w; sq.y += mv.y * mv.y * w;
                sq.z += mv.z * mv.z * w; sq.w += mv.w * mv.w * w;
                mx.x = fmaxf(mx.x, wm.x); mx.y = fmaxf(mx.y, wm.y);
                mx.z = fmaxf(mx.z, wm.z); mx.w = fmaxf(mx.w, wm.w);
                mn.x = fminf(mn.x, wm.x); mn.y = fminf(mn.y, wm.y);
                mn.z = fminf(mn.z, wm.z); mn.w = fminf(mn.w, wm.w);
                if (LAST) {
                    float sc = w * Dv;
                    if (sc > bestS) { bestS = sc; bestSrc = src; }
                    else if (sc == bestS) bestSrc = min(bestSrc, src);
                }
            }
        }
    }

    // combine quarters (xor 8, 16)
    #pragma unroll
    for (int o = 8; o <= 16; o <<= 1) {
        sum.x += __shfl_xor_sync(0xffffffffu, sum.x, o);
        sum.y += __shfl_xor_sync(0xffffffffu, sum.y, o);
        sum.z += __shfl_xor_sync(0xffffffffu, sum.z, o);
        sum.w += __shfl_xor_sync(0xffffffffu, sum.w, o);
        sq.x += __shfl_xor_sync(0xffffffffu, sq.x, o);
        sq.y += __shfl_xor_sync(0xffffffffu, sq.y, o);
        sq.z += __shfl_xor_sync(0xffffffffu, sq.z, o);
        sq.w += __shfl_xor_sync(0xffffffffu, sq.w, o);
        mx.x = fmaxf(mx.x, __shfl_xor_sync(0xffffffffu, mx.x, o));
        mx.y = fmaxf(mx.y, __shfl_xor_sync(0xffffffffu, mx.y, o));
        mx.z = fmaxf(mx.z, __shfl_xor_sync(0xffffffffu, mx.z, o));
        mx.w = fmaxf(mx.w, __shfl_xor_sync(0xffffffffu, mx.w, o));
        mn.x = fminf(mn.x, __shfl_xor_sync(0xffffffffu, mn.x, o));
        mn.y = fminf(mn.y, __shfl_xor_sync(0xffffffffu, mn.y, o));
        mn.z = fminf(mn.z, __shfl_xor_sync(0xffffffffu, mn.z, o));
        mn.w = fminf(mn.w, __shfl_xor_sync(0xffffffffu, mn.w, o));
        if (LAST) {
            float oS = __shfl_xor_sync(0xffffffffu, bestS, o);
            int oI = __shfl_xor_sync(0xffffffffu, bestSrc, o);
            if (oS > bestS) { bestS = oS; bestSrc = oI; }
            else if (oS == bestS) bestSrc = min(bestSrc, oI);
        }
    }

    float c = (float)(cnt + 1);
    float4 mean, sd;
    mean.x = sum.x / c; mean.y = sum.y / c; mean.z = sum.z / c; mean.w = sum.w / c;
    sd.x = sqrtf(fmaxf(sq.x / c - mean.x * mean.x, 1e-6f));
    sd.y = sqrtf(fmaxf(sq.y / c - mean.y * mean.y, 1e-6f));
    sd.z = sqrtf(fmaxf(sq.z / c - mean.z * mean.z, 1e-6f));
    sd.w = sqrtf(fmaxf(sq.w / c - mean.w * mean.w, 1e-6f));

    if (q == 0) {
        // h part: dims 4r..4r+3
        float4 hv = *reinterpret_cast<const float4*>(&hin[n * Dd + 4 * r]);
        union { __nv_bfloat16 v[4]; uint2 u; } hh, hl;
        float hvv[4] = {hv.x, hv.y, hv.z, hv.w};
        #pragma unroll
        for (int t = 0; t < 4; t++) {
            __nv_bfloat16 a = __float2bfloat16_rn(hvv[t]);
            hh.v[t] = a;
            hl.v[t] = __float2bfloat16_rn(hvv[t] - __bfloat162float(a));
        }
        *reinterpret_cast<uint2*>(&g_Xh[n * KK + 4 * r]) = hh.u;
        *reinterpret_cast<uint2*>(&g_Xl[n * KK + 4 * r]) = hl.u;

        // feats: 16 values, dims 4r..4r+3 x {mean,max,min,std}
        float fv[16] = {mean.x, mx.x, mn.x, sd.x,  mean.y, mx.y, mn.y, sd.y,
                        mean.z, mx.z, mn.z, sd.z,  mean.w, mx.w, mn.w, sd.w};
        union { __nv_bfloat16 v[16]; uint4 u2[2]; } fh, fl;
        #pragma unroll
        for (int t = 0; t < 16; t++) {
            __nv_bfloat16 a = __float2bfloat16_rn(fv[t]);
            fh.v[t] = a;
            fl.v[t] = __float2bfloat16_rn(fv[t] - __bfloat162float(a));
        }
        uint4* dh = reinterpret_cast<uint4*>(&g_Xh[n * KK + Dd + 16 * r]);
        uint4* dl = reinterpret_cast<uint4*>(&g_Xl[n * KK + Dd + 16 * r]);
        dh[0] = fh.u2[0]; dh[1] = fh.u2[1];
        dl[0] = fl.u2[0]; dl[1] = fl.u2[1];
    }
    if (LAST && lane == 0) g_pred[n] = bestSrc;
}

// ---------------- tensor-core GEMM + fused epilogue ----------------
__global__ void k_gemm(const float* __restrict__ linb, int layer, int outsel) {
    extern __shared__ char sm_[];
    __nv_bfloat16* Bh = reinterpret_cast<__nv_bfloat16*>(sm_);
    __nv_bfloat16* Bl = Bh + KK * B_LD;
    __nv_bfloat16* Ah = Bl + KK * B_LD;
    __nv_bfloat16* Al = Ah + BM * A_LD;
    float* Cs = reinterpret_cast<float*>(sm_);

    float* __restrict__ hout = hbuf(outsel);
    int row0 = blockIdx.x * BM;
    int wid = threadIdx.x >> 5;

    {
        const uint4* srcH = reinterpret_cast<const uint4*>(g_Wbh + layer * KK * CN);
        const uint4* srcL = reinterpret_cast<const uint4*>(g_Wbl + layer * KK * CN);
        for (int i = threadIdx.x; i < KK * CN / 8; i += 256) {
            int r = i / 12, c = i % 12;
            reinterpret_cast<uint4*>(Bh + r * B_LD)[c] = srcH[i];
            reinterpret_cast<uint4*>(Bl + r * B_LD)[c] = srcL[i];
        }
    }

    wmma::fragment<wmma::accumulator, 16, 16, 16, float> acc[6];
    #pragma unroll
    for (int t = 0; t < 6; t++) wmma::fill_fragment(acc[t], 0.0f);

    for (int kt = 0; kt < KK; kt += 32) {
        __syncthreads();
        for (int i = threadIdx.x; i < BM * 32 / 8; i += 256) {
            int r = i >> 2, c = i & 3;
            size_t goff = (size_t)(row0 + r) * KK + kt + c * 8;
            reinterpret_cast<uint4*>(Ah + r * A_LD)[c] =
                *reinterpret_cast<const uint4*>(g_Xh + goff);
            reinterpret_cast<uint4*>(Al + r * A_LD)[c] =
                *reinterpret_cast<const uint4*>(g_Xl + goff);
        }
        __syncthreads();

        #pragma unroll
        for (int ks = 0; ks < 32; ks += 16) {
            wmma::fragment<wmma::matrix_a, 16, 16, 16, __nv_bfloat16, wmma::row_major> ah, al;
            wmma::load_matrix_sync(ah, Ah + wid * 16 * A_LD + ks, A_LD);
            wmma::load_matrix_sync(al, Al + wid * 16 * A_LD + ks, A_LD);
            #pragma unroll
            for (int t = 0; t < 6; t++) {
                wmma::fragment<wmma::matrix_b, 16, 16, 16, __nv_bfloat16, wmma::row_major> bh, bl;
                wmma::load_matrix_sync(bh, Bh + (kt + ks) * B_LD + t * 16, B_LD);
                wmma::load_matrix_sync(bl, Bl + (kt + ks) * B_LD + t * 16, B_LD);
                wmma::mma_sync(acc[t], ah, bh, acc[t]);
                wmma::mma_sync(acc[t], ah, bl, acc[t]);
                wmma::mma_sync(acc[t], al, bh, acc[t]);
            }
        }
    }

    __syncthreads();
    #pragma unroll
    for (int t = 0; t < 6; t++)
        wmma::store_matrix_sync(Cs + wid * 16 * CN + t * 16, acc[t], CN, wmma::mem_row_major);
    __syncthreads();

    for (int i = threadIdx.x; i < BM * Dd; i += 256) {
        int r = i >> 5, d = i & 31;
        int n = row0 + r;
        if (n < Nn) {
            float s = g_scale[n];
            float inv = 1.0f / fmaxf(s, 0.01f);
            float v = Cs[r * CN + d] + s * Cs[r * CN + 32 + d] + inv * Cs[r * CN + 64 + d]
                      + linb[layer * Dd + d];
            hout[n * Dd + d] = fmaxf(v, 0.0f);
        }
    }
}

// ---------------- final MLP + output assembly ----------------
__global__ void k_final(int insel, const float* __restrict__ q,
                        const float* __restrict__ W1, const float* __restrict__ b1,
                        const float* __restrict__ W2, const float* __restrict__ b2,
                        float* __restrict__ out) {
    __shared__ float sW1[64 * 64];
    __shared__ float sW2[64];
    __shared__ float sb1[64];
    __shared__ float sq[32];
    int tid = threadIdx.x;
    for (int i = tid; i < 4096; i += 256) sW1[i] = W1[i];
    if (tid < 64) { sW2[tid] = W2[tid]; sb1[tid] = b1[tid]; }
    if (tid < 32) sq[tid] = q[tid];
    __syncthreads();

    const float* __restrict__ hfin = hbuf(insel);
    int warp = (blockIdx.x * blockDim.x + tid) >> 5;
    int lane = tid & 31;
    if (warp >= Nn) return;
    int n = warp;
    float hv = hfin[n * Dd + lane];
    float a0 = sb1[lane], a1 = sb1[lane + 32];
    #pragma unroll
    for (int k = 0; k < 32; k++) {
        float xv = __shfl_sync(0xffffffffu, hv, k);
        a0 += xv * sW1[k * 64 + lane];
        a1 += xv * sW1[k * 64 + 32 + lane];
    }
    #pragma unroll
    for (int k = 0; k < 32; k++) {
        float xv = sq[k];
        a0 += xv * sW1[(32 + k) * 64 + lane];
        a1 += xv * sW1[(32 + k) * 64 + 32 + lane];
    }
    a0 = fmaxf(a0, 0.0f);
    a1 = fmaxf(a1, 0.0f);
    float p = a0 * sW2[lane] + a1 * sW2[lane + 32];
    #pragma unroll
    for (int o = 16; o; o >>= 1) p += __shfl_xor_sync(0xffffffffu, p, o);
    if (lane == 0) {
        out[n] = p + b2[0];
        out[Nn + n] = (float)g_pred[n];
    }
}

// ---------------- launch ----------------
extern "C" void kernel_launch(void* const* d_in, const int* in_sizes, int n_in,
                              void* d_out, int out_size) {
    const int*   node_in  = (const int*)d_in[0];
    const int*   node_out = (const int*)d_in[1];
    const float* ew       = (const float*)d_in[2];
    const int*   hptr     = (const int*)d_in[3];
    const float* qw       = (const float*)d_in[4];
    const float* relW     = (const float*)d_in[5];
    const float* relb     = (const float*)d_in[6];
    const float* linW     = (const float*)d_in[7];
    const float* linb     = (const float*)d_in[8];
    const float* W1       = (const float*)d_in[9];
    const float* b1       = (const float*)d_in[10];
    const float* W2       = (const float*)d_in[11];
    const float* b2       = (const float*)d_in[12];
    float* out = (float*)d_out;

    static bool attr_set = false;
    if (!attr_set) {
        cudaFuncSetAttribute(k_gemm, cudaFuncAttributeMaxDynamicSharedMemorySize, GEMM_SMEM);
        attr_set = true;
    }

    k_init<<<(Nn * Dd + 255) / 256, 256>>>(hptr, qw, relW, relb, linW);
    k_count<<<(Ee + 255) / 256, 256>>>(node_out, ew);
    k_alloc<<<(Nn + 255) / 256, 256>>>();
    k_scatter<<<(Ee + 255) / 256, 256>>>(node_out, node_in, ew);

    int cur = 0;
    for (int l = 0; l < NL; l++) {
        if (l == NL - 1) {
            k_dot<<<(Nn + 7) / 8, 256>>>(cur, l);
            k_agg<1><<<(Nn + 7) / 8, 256>>>(hptr, cur, l);
        } else {
            k_agg<0><<<(Nn + 7) / 8, 256>>>(hptr, cur, l);
        }
        k_gemm<<<(NR / BM), 256, GEMM_SMEM>>>(linb, l, cur ^ 1);
        cur ^= 1;
    }
    k_final<<<(Nn + 7) / 8, 256>>>(cur, qw, W1, b1, W2, b2, out);
}

// round 5
// speedup vs baseline: 1.0631x; 1.0631x over previous
#include <cuda_runtime.h>
#include <cuda_bf16.h>
#include <mma.h>
#include <math.h>

using namespace nvcuda;

#define Nn 50000
#define NR 50048
#define Ee 800000
#define Dd 32
#define NL 6
#define KK 160
#define CN 96
#define BM 128
#define A_LD 40
#define B_LD 104
#define GEMM_SMEM ((2*KK*B_LD + 2*BM*A_LD) * 2)

// ---------------- device scratch ----------------
__device__ float g_h0[Nn * Dd];
__device__ float g_h1[Nn * Dd];
__device__ __nv_bfloat16 g_Xh[NR * KK];
__device__ __nv_bfloat16 g_Xl[NR * KK];
__device__ __nv_bfloat16 g_Wbh[NL * KK * CN];
__device__ __nv_bfloat16 g_Wbl[NL * KK * CN];
__device__ float g_scale[Nn];
__device__ float g_deg[Nn];
__device__ int   g_indeg[Nn];
__device__ int   g_start[Nn];
__device__ int   g_cursor[Nn];
__device__ int2  g_csr[Ee];
__device__ float g_rel[NL * Dd];
__device__ float g_D[Nn];
__device__ float g_sum;
__device__ int   g_tot;
__device__ int   g_pred[Nn];

__device__ __forceinline__ float* hbuf(int s) { return s ? g_h1 : g_h0; }

// ---------------- init: boundary, counters, rel, Wc build ----------------
__global__ void k_init(const int* __restrict__ hptr, const float* __restrict__ q,
                       const float* __restrict__ relW, const float* __restrict__ relb,
                       const float* __restrict__ linW) {
    int idx = blockIdx.x * blockDim.x + threadIdx.x;
    if (idx < Nn * Dd) {
        int n = idx >> 5;
        int h = *hptr;
        g_h0[idx] = (n == h) ? 0.0f : 100.0f;
        if ((idx & 31) == 0) {
            g_deg[n] = 1.0f;
            g_indeg[n] = 0;
        }
    }
    if (idx < NL * KK * CN) {
        int l = idx / (KK * CN);
        int rem = idx % (KK * CN);
        int k = rem / CN;
        int j = rem % CN;
        float v;
        if (k < 32) {
            v = (j < 32) ? linW[(l * 416 + k) * 32 + j] : 0.0f;
        } else {
            int f = k - 32, g = j >> 5, d = j & 31;
            v = linW[(l * 416 + 32 + f * 3 + g) * 32 + d];
        }
        __nv_bfloat16 hh = __float2bfloat16_rn(v);
        g_Wbh[idx] = hh;
        g_Wbl[idx] = __float2bfloat16_rn(v - __bfloat162float(hh));
    }
    if (idx < NL * Dd) {
        int i = idx >> 5, d = idx & 31;
        float acc = relb[i * Dd + d];
        for (int k = 0; k < Dd; k++)
            acc += q[k] * relW[(i * Dd + k) * Dd + d];
        g_rel[i * Dd + d] = acc;
    }
    if (idx == 0) { g_sum = 0.0f; g_tot = 0; }
}

// ---------------- edge counting ----------------
__global__ void k_count(const int* __restrict__ node_out, const float* __restrict__ ew) {
    int e = blockIdx.x * blockDim.x + threadIdx.x;
    if (e >= Ee) return;
    int o = node_out[e];
    atomicAdd(&g_deg[o], ew[e]);
    atomicAdd(&g_indeg[o], 1);
}

// ---------------- segment allocation + log(deg) partial sum ----------------
__global__ void k_alloc() {
    int i = blockIdx.x * blockDim.x + threadIdx.x;
    float s = 0.0f;
    if (i < Nn) {
        int c = g_indeg[i];
        int st = atomicAdd(&g_tot, c);
        g_start[i] = st;
        g_cursor[i] = st;
        s = logf(g_deg[i]);
        g_scale[i] = s;
    }
    for (int o = 16; o; o >>= 1) s += __shfl_xor_sync(0xffffffffu, s, o);
    __shared__ float wsum[8];
    int lane = threadIdx.x & 31, wid = threadIdx.x >> 5;
    if (lane == 0) wsum[wid] = s;
    __syncthreads();
    if (threadIdx.x == 0) {
        float t = 0.0f;
        for (int w = 0; w < 8; w++) t += wsum[w];
        atomicAdd(&g_sum, t);
    }
}

// ---------------- CSR scatter + scale normalize ----------------
__global__ void k_scatter(const int* __restrict__ node_out, const int* __restrict__ node_in,
                          const float* __restrict__ ew) {
    int e = blockIdx.x * blockDim.x + threadIdx.x;
    if (e < Nn) g_scale[e] = g_scale[e] * ((float)Nn / g_sum);
    if (e >= Ee) return;
    int n = node_out[e];
    int p = atomicAdd(&g_cursor[n], 1);
    g_csr[p] = make_int2(node_in[e], __float_as_int(ew[e]));
}

// ---------------- per-node dot(h, rel) ----------------
__global__ void k_dot(int insel, int layer) {
    int warp = (blockIdx.x * blockDim.x + threadIdx.x) >> 5;
    int lane = threadIdx.x & 31;
    if (warp >= Nn) return;
    const float* __restrict__ hin = hbuf(insel);
    float v = hin[warp * Dd + lane] * g_rel[layer * Dd + lane];
    #pragma unroll
    for (int o = 16; o; o >>= 1) v += __shfl_xor_sync(0xffffffffu, v, o);
    if (lane == 0) g_D[warp] = v;
}

// ---------------- aggregation: warp per node, lane = dim, MLP=8 ----------------
template <int LAST>
__global__ void k_agg(const int* __restrict__ hptr, int insel, int layer) {
    int warp = (blockIdx.x * blockDim.x + threadIdx.x) >> 5;
    int lane = threadIdx.x & 31;
    if (warp >= Nn) return;
    int n = warp;
    const float* __restrict__ hin = hbuf(insel);
    int h = *hptr;
    float relv = g_rel[layer * Dd + lane];

    float b = (n == h) ? 0.0f : 100.0f;
    float sum = b, sq = b * b, mx = b, mn = b;
    float bestS = 32.0f * b;
    int bestSrc = n;

    int st = g_start[n];
    int cnt = g_indeg[n];
    for (int base = 0; base < cnt; base += 32) {
        int rem = cnt - base;
        int m = rem < 32 ? rem : 32;
        int2 ed = make_int2(0, 0);
        if (lane < m) ed = g_csr[st + base + lane];

        int j = 0;
        for (; j + 8 <= m; j += 8) {
            int s0 = __shfl_sync(0xffffffffu, ed.x, j + 0);
            int s1 = __shfl_sync(0xffffffffu, ed.x, j + 1);
            int s2 = __shfl_sync(0xffffffffu, ed.x, j + 2);
            int s3 = __shfl_sync(0xffffffffu, ed.x, j + 3);
            int s4 = __shfl_sync(0xffffffffu, ed.x, j + 4);
            int s5 = __shfl_sync(0xffffffffu, ed.x, j + 5);
            int s6 = __shfl_sync(0xffffffffu, ed.x, j + 6);
            int s7 = __shfl_sync(0xffffffffu, ed.x, j + 7);
            float w0 = __int_as_float(__shfl_sync(0xffffffffu, ed.y, j + 0));
            float w1 = __int_as_float(__shfl_sync(0xffffffffu, ed.y, j + 1));
            float w2 = __int_as_float(__shfl_sync(0xffffffffu, ed.y, j + 2));
            float w3 = __int_as_float(__shfl_sync(0xffffffffu, ed.y, j + 3));
            float w4 = __int_as_float(__shfl_sync(0xffffffffu, ed.y, j + 4));
            float w5 = __int_as_float(__shfl_sync(0xffffffffu, ed.y, j + 5));
            float w6 = __int_as_float(__shfl_sync(0xffffffffu, ed.y, j + 6));
            float w7 = __int_as_float(__shfl_sync(0xffffffffu, ed.y, j + 7));
            // issue all gathers before accumulating (MLP=8)
            float v0 = hin[s0 * Dd + lane];
            float v1 = hin[s1 * Dd + lane];
            float v2 = hin[s2 * Dd + lane];
            float v3 = hin[s3 * Dd + lane];
            float v4 = hin[s4 * Dd + lane];
            float v5 = hin[s5 * Dd + lane];
            float v6 = hin[s6 * Dd + lane];
            float v7 = hin[s7 * Dd + lane];
            float D0 = 0.f, D1 = 0.f, D2 = 0.f, D3 = 0.f;
            float D4 = 0.f, D5 = 0.f, D6 = 0.f, D7 = 0.f;
            if (LAST) {
                D0 = g_D[s0]; D1 = g_D[s1]; D2 = g_D[s2]; D3 = g_D[s3];
                D4 = g_D[s4]; D5 = g_D[s5]; D6 = g_D[s6]; D7 = g_D[s7];
            }

            float m0 = v0 * relv, wm0 = m0 * w0;
            sum += wm0; sq += m0 * m0 * w0; mx = fmaxf(mx, wm0); mn = fminf(mn, wm0);
            float m1 = v1 * relv, wm1 = m1 * w1;
            sum += wm1; sq += m1 * m1 * w1; mx = fmaxf(mx, wm1); mn = fminf(mn, wm1);
            float m2 = v2 * relv, wm2 = m2 * w2;
            sum += wm2; sq += m2 * m2 * w2; mx = fmaxf(mx, wm2); mn = fminf(mn, wm2);
            float m3 = v3 * relv, wm3 = m3 * w3;
            sum += wm3; sq += m3 * m3 * w3; mx = fmaxf(mx, wm3); mn = fminf(mn, wm3);
            float m4 = v4 * relv, wm4 = m4 * w4;
            sum += wm4; sq += m4 * m4 * w4; mx = fmaxf(mx, wm4); mn = fminf(mn, wm4);
            float m5 = v5 * relv, wm5 = m5 * w5;
            sum += wm5; sq += m5 * m5 * w5; mx = fmaxf(mx, wm5); mn = fminf(mn, wm5);
            float m6 = v6 * relv, wm6 = m6 * w6;
            sum += wm6; sq += m6 * m6 * w6; mx = fmaxf(mx, wm6); mn = fminf(mn, wm6);
            float m7 = v7 * relv, wm7 = m7 * w7;
            sum += wm7; sq += m7 * m7 * w7; mx = fmaxf(mx, wm7); mn = fminf(mn, wm7);

            if (LAST) {
                float sc;
                sc = w0 * D0;
                if (sc > bestS) { bestS = sc; bestSrc = s0; }
                else if (sc == bestS) bestSrc = min(bestSrc, s0);
                sc = w1 * D1;
                if (sc > bestS) { bestS = sc; bestSrc = s1; }
                else if (sc == bestS) bestSrc = min(bestSrc, s1);
                sc = w2 * D2;
                if (sc > bestS) { bestS = sc; bestSrc = s2; }
                else if (sc == bestS) bestSrc = min(bestSrc, s2);
                sc = w3 * D3;
                if (sc > bestS) { bestS = sc; bestSrc = s3; }
                else if (sc == bestS) bestSrc = min(bestSrc, s3);
                sc = w4 * D4;
                if (sc > bestS) { bestS = sc; bestSrc = s4; }
                else if (sc == bestS) bestSrc = min(bestSrc, s4);
                sc = w5 * D5;
                if (sc > bestS) { bestS = sc; bestSrc = s5; }
                else if (sc == bestS) bestSrc = min(bestSrc, s5);
                sc = w6 * D6;
                if (sc > bestS) { bestS = sc; bestSrc = s6; }
                else if (sc == bestS) bestSrc = min(bestSrc, s6);
                sc = w7 * D7;
                if (sc > bestS) { bestS = sc; bestSrc = s7; }
                else if (sc == bestS) bestSrc = min(bestSrc, s7);
            }
        }
        for (; j < m; j++) {
            int s0 = __shfl_sync(0xffffffffu, ed.x, j);
            float w0 = __int_as_float(__shfl_sync(0xffffffffu, ed.y, j));
            float m0 = hin[s0 * Dd + lane] * relv;
            float wm0 = m0 * w0;
            sum += wm0; sq += m0 * m0 * w0;
            mx = fmaxf(mx, wm0); mn = fminf(mn, wm0);
            if (LAST) {
                float sc = w0 * g_D[s0];
                if (sc > bestS) { bestS = sc; bestSrc = s0; }
                else if (sc == bestS) bestSrc = min(bestSrc, s0);
            }
        }
    }
    float c = (float)(cnt + 1);
    float mean = sum / c;
    float sqm = sq / c;
    float sd = sqrtf(fmaxf(sqm - mean * mean, 1e-6f));

    // write split-bf16 GEMM row: [h(32) | feats(128)]
    float hv = hin[n * Dd + lane];
    __nv_bfloat16 hh = __float2bfloat16_rn(hv);
    g_Xh[n * KK + lane] = hh;
    g_Xl[n * KK + lane] = __float2bfloat16_rn(hv - __bfloat162float(hh));

    union { __nv_bfloat16 v[4]; uint2 u; } ph, pl;
    float fv[4] = {mean, mx, mn, sd};
    #pragma unroll
    for (int t = 0; t < 4; t++) {
        __nv_bfloat16 fh = __float2bfloat16_rn(fv[t]);
        ph.v[t] = fh;
        pl.v[t] = __float2bfloat16_rn(fv[t] - __bfloat162float(fh));
    }
    *reinterpret_cast<uint2*>(&g_Xh[n * KK + Dd + lane * 4]) = ph.u;
    *reinterpret_cast<uint2*>(&g_Xl[n * KK + Dd + lane * 4]) = pl.u;

    if (LAST && lane == 0) g_pred[n] = bestSrc;
}

// ---------------- tensor-core GEMM + fused epilogue ----------------
__global__ void k_gemm(const float* __restrict__ linb, int layer, int outsel) {
    extern __shared__ char sm_[];
    __nv_bfloat16* Bh = reinterpret_cast<__nv_bfloat16*>(sm_);
    __nv_bfloat16* Bl = Bh + KK * B_LD;
    __nv_bfloat16* Ah = Bl + KK * B_LD;
    __nv_bfloat16* Al = Ah + BM * A_LD;
    float* Cs = reinterpret_cast<float*>(sm_);

    float* __restrict__ hout = hbuf(outsel);
    int row0 = blockIdx.x * BM;
    int wid = threadIdx.x >> 5;

    {
        const uint4* srcH = reinterpret_cast<const uint4*>(g_Wbh + layer * KK * CN);
        const uint4* srcL = reinterpret_cast<const uint4*>(g_Wbl + layer * KK * CN);
        for (int i = threadIdx.x; i < KK * CN / 8; i += 256) {
            int r = i / 12, c = i % 12;
            reinterpret_cast<uint4*>(Bh + r * B_LD)[c] = srcH[i];
            reinterpret_cast<uint4*>(Bl + r * B_LD)[c] = srcL[i];
        }
    }

    wmma::fragment<wmma::accumulator, 16, 16, 16, float> acc[6];
    #pragma unroll
    for (int t = 0; t < 6; t++) wmma::fill_fragment(acc[t], 0.0f);

    for (int kt = 0; kt < KK; kt += 32) {
        __syncthreads();
        for (int i = threadIdx.x; i < BM * 32 / 8; i += 256) {
            int r = i >> 2, c = i & 3;
            size_t goff = (size_t)(row0 + r) * KK + kt + c * 8;
            reinterpret_cast<uint4*>(Ah + r * A_LD)[c] =
                *reinterpret_cast<const uint4*>(g_Xh + goff);
            reinterpret_cast<uint4*>(Al + r * A_LD)[c] =
                *reinterpret_cast<const uint4*>(g_Xl + goff);
        }
        __syncthreads();

        #pragma unroll
        for (int ks = 0; ks < 32; ks += 16) {
            wmma::fragment<wmma::matrix_a, 16, 16, 16, __nv_bfloat16, wmma::row_major> ah, al;
            wmma::load_matrix_sync(ah, Ah + wid * 16 * A_LD + ks, A_LD);
            wmma::load_matrix_sync(al, Al + wid * 16 * A_LD + ks, A_LD);
            #pragma unroll
            for (int t = 0; t < 6; t++) {
                wmma::fragment<wmma::matrix_b, 16, 16, 16, __nv_bfloat16, wmma::row_major> bh, bl;
                wmma::load_matrix_sync(bh, Bh + (kt + ks) * B_LD + t * 16, B_LD);
                wmma::load_matrix_sync(bl, Bl + (kt + ks) * B_LD + t * 16, B_LD);
                wmma::mma_sync(acc[t], ah, bh, acc[t]);
                wmma::mma_sync(acc[t], ah, bl, acc[t]);
                wmma::mma_sync(acc[t], al, bh, acc[t]);
            }
        }
    }

    __syncthreads();
    #pragma unroll
    for (int t = 0; t < 6; t++)
        wmma::store_matrix_sync(Cs + wid * 16 * CN + t * 16, acc[t], CN, wmma::mem_row_major);
    __syncthreads();

    for (int i = threadIdx.x; i < BM * Dd; i += 256) {
        int r = i >> 5, d = i & 31;
        int n = row0 + r;
        if (n < Nn) {
            float s = g_scale[n];
            float inv = 1.0f / fmaxf(s, 0.01f);
            float v = Cs[r * CN + d] + s * Cs[r * CN + 32 + d] + inv * Cs[r * CN + 64 + d]
                      + linb[layer * Dd + d];
            hout[n * Dd + d] = fmaxf(v, 0.0f);
        }
    }
}

// ---------------- final MLP + output assembly ----------------
__global__ void k_final(int insel, const float* __restrict__ q,
                        const float* __restrict__ W1, const float* __restrict__ b1,
                        const float* __restrict__ W2, const float* __restrict__ b2,
                        float* __restrict__ out) {
    __shared__ float sW1[64 * 64];
    __shared__ float sW2[64];
    __shared__ float sb1[64];
    __shared__ float sq[32];
    int tid = threadIdx.x;
    for (int i = tid; i < 4096; i += 256) sW1[i] = W1[i];
    if (tid < 64) { sW2[tid] = W2[tid]; sb1[tid] = b1[tid]; }
    if (tid < 32) sq[tid] = q[tid];
    __syncthreads();

    const float* __restrict__ hfin = hbuf(insel);
    int warp = (blockIdx.x * blockDim.x + tid) >> 5;
    int lane = tid & 31;
    if (warp >= Nn) return;
    int n = warp;
    float hv = hfin[n * Dd + lane];
    float a0 = sb1[lane], a1 = sb1[lane + 32];
    #pragma unroll
    for (int k = 0; k < 32; k++) {
        float xv = __shfl_sync(0xffffffffu, hv, k);
        a0 += xv * sW1[k * 64 + lane];
        a1 += xv * sW1[k * 64 + 32 + lane];
    }
    #pragma unroll
    for (int k = 0; k < 32; k++) {
        float xv = sq[k];
        a0 += xv * sW1[(32 + k) * 64 + lane];
        a1 += xv * sW1[(32 + k) * 64 + 32 + lane];
    }
    a0 = fmaxf(a0, 0.0f);
    a1 = fmaxf(a1, 0.0f);
    float p = a0 * sW2[lane] + a1 * sW2[lane + 32];
    #pragma unroll
    for (int o = 16; o; o >>= 1) p += __shfl_xor_sync(0xffffffffu, p, o);
    if (lane == 0) {
        out[n] = p + b2[0];
        out[Nn + n] = (float)g_pred[n];
    }
}

// ---------------- launch ----------------
extern "C" void kernel_launch(void* const* d_in, const int* in_sizes, int n_in,
                              void* d_out, int out_size) {
    const int*   node_in  = (const int*)d_in[0];
    const int*   node_out = (const int*)d_in[1];
    const float* ew       = (const float*)d_in[2];
    const int*   hptr     = (const int*)d_in[3];
    const float* qw       = (const float*)d_in[4];
    const float* relW     = (const float*)d_in[5];
    const float* relb     = (const float*)d_in[6];
    const float* linW     = (const float*)d_in[7];
    const float* linb     = (const float*)d_in[8];
    const float* W1       = (const float*)d_in[9];
    const float* b1       = (const float*)d_in[10];
    const float* W2       = (const float*)d_in[11];
    const float* b2       = (const float*)d_in[12];
    float* out = (float*)d_out;

    static bool attr_set = false;
    if (!attr_set) {
        cudaFuncSetAttribute(k_gemm, cudaFuncAttributeMaxDynamicSharedMemorySize, GEMM_SMEM);
        attr_set = true;
    }

    k_init<<<(Nn * Dd + 255) / 256, 256>>>(hptr, qw, relW, relb, linW);
    k_count<<<(Ee + 255) / 256, 256>>>(node_out, ew);
    k_alloc<<<(Nn + 255) / 256, 256>>>();
    k_scatter<<<(Ee + 255) / 256, 256>>>(node_out, node_in, ew);

    int cur = 0;
    for (int l = 0; l < NL; l++) {
        if (l == NL - 1) {
            k_dot<<<(Nn + 7) / 8, 256>>>(cur, l);
            k_agg<1><<<(Nn + 7) / 8, 256>>>(hptr, cur, l);
        } else {
            k_agg<0><<<(Nn + 7) / 8, 256>>>(hptr, cur, l);
        }
        k_gemm<<<(NR / BM), 256, GEMM_SMEM>>>(linb, l, cur ^ 1);
        cur ^= 1;
    }
    k_final<<<(Nn + 7) / 8, 256>>>(cur, qw, W1, b1, W2, b2, out);
}

// round 6
// speedup vs baseline: 1.1202x; 1.0536x over previous
#include <cuda_runtime.h>
#include <cuda_bf16.h>
#include <mma.h>
#include <math.h>

using namespace nvcuda;

#define Nn 50000
#define NR 50048
#define Ee 800000
#define Dd 32
#define NL 6
#define KK 160
#define CN 96
#define BM 128
#define A_LD 40
#define B_LD 104
#define GEMM_SMEM ((2*KK*B_LD + 2*BM*A_LD) * 2)

// ---------------- device scratch ----------------
__device__ float g_h0[Nn * Dd];
__device__ float g_h1[Nn * Dd];
__device__ __nv_bfloat16 g_Xh[NR * KK];
__device__ __nv_bfloat16 g_Xl[NR * KK];
__device__ __nv_bfloat16 g_Wbh[NL * KK * CN];
__device__ __nv_bfloat16 g_Wbl[NL * KK * CN];
__device__ float g_scale[Nn];
__device__ float g_deg[Nn];
__device__ int   g_indeg[Nn];
__device__ int   g_start[Nn];
__device__ int   g_cursor[Nn];
__device__ int2  g_csr[Ee];
__device__ float g_rel[NL * Dd];
__device__ float g_D[Nn];
__device__ float g_sum;
__device__ int   g_tot;
__device__ int   g_pred[Nn];

__device__ __forceinline__ float* hbuf(int s) { return s ? g_h1 : g_h0; }

// ---------------- init: boundary, counters, rel, Wc build ----------------
__global__ void k_init(const int* __restrict__ hptr, const float* __restrict__ q,
                       const float* __restrict__ relW, const float* __restrict__ relb,
                       const float* __restrict__ linW) {
    int idx = blockIdx.x * blockDim.x + threadIdx.x;
    if (idx < Nn * Dd) {
        int n = idx >> 5;
        int h = *hptr;
        g_h0[idx] = (n == h) ? 0.0f : 100.0f;
        if ((idx & 31) == 0) {
            g_deg[n] = 1.0f;
            g_indeg[n] = 0;
        }
    }
    if (idx < NL * KK * CN) {
        int l = idx / (KK * CN);
        int rem = idx % (KK * CN);
        int k = rem / CN;
        int j = rem % CN;
        float v;
        if (k < 32) {
            v = (j < 32) ? linW[(l * 416 + k) * 32 + j] : 0.0f;
        } else {
            int f = k - 32, g = j >> 5, d = j & 31;
            v = linW[(l * 416 + 32 + f * 3 + g) * 32 + d];
        }
        __nv_bfloat16 hh = __float2bfloat16_rn(v);
        g_Wbh[idx] = hh;
        g_Wbl[idx] = __float2bfloat16_rn(v - __bfloat162float(hh));
    }
    if (idx < NL * Dd) {
        int i = idx >> 5, d = idx & 31;
        float acc = relb[i * Dd + d];
        for (int k = 0; k < Dd; k++)
            acc += q[k] * relW[(i * Dd + k) * Dd + d];
        g_rel[i * Dd + d] = acc;
    }
    if (idx == 0) { g_sum = 0.0f; g_tot = 0; }
}

// ---------------- edge counting ----------------
__global__ void k_count(const int* __restrict__ node_out, const float* __restrict__ ew) {
    int e = blockIdx.x * blockDim.x + threadIdx.x;
    if (e >= Ee) return;
    int o = node_out[e];
    atomicAdd(&g_deg[o], ew[e]);
    atomicAdd(&g_indeg[o], 1);
}

// ---------------- segment allocation + log(deg) partial sum ----------------
__global__ void k_alloc() {
    int i = blockIdx.x * blockDim.x + threadIdx.x;
    float s = 0.0f;
    if (i < Nn) {
        int c = g_indeg[i];
        int st = atomicAdd(&g_tot, c);
        g_start[i] = st;
        g_cursor[i] = st;
        s = logf(g_deg[i]);
        g_scale[i] = s;
    }
    for (int o = 16; o; o >>= 1) s += __shfl_xor_sync(0xffffffffu, s, o);
    __shared__ float wsum[8];
    int lane = threadIdx.x & 31, wid = threadIdx.x >> 5;
    if (lane == 0) wsum[wid] = s;
    __syncthreads();
    if (threadIdx.x == 0) {
        float t = 0.0f;
        for (int w = 0; w < 8; w++) t += wsum[w];
        atomicAdd(&g_sum, t);
    }
}

// ---------------- CSR scatter + scale normalize ----------------
__global__ void k_scatter(const int* __restrict__ node_out, const int* __restrict__ node_in,
                          const float* __restrict__ ew) {
    int e = blockIdx.x * blockDim.x + threadIdx.x;
    if (e < Nn) g_scale[e] = g_scale[e] * ((float)Nn / g_sum);
    if (e >= Ee) return;
    int n = node_out[e];
    int p = atomicAdd(&g_cursor[n], 1);
    g_csr[p] = make_int2(node_in[e], __float_as_int(ew[e]));
}

// ---------------- aggregation: warp per node, lane = dim, MLP=4 (R2 body) -----
template <int LAST>
__global__ void k_agg(const int* __restrict__ hptr, int insel, int layer) {
    int warp = (blockIdx.x * blockDim.x + threadIdx.x) >> 5;
    int lane = threadIdx.x & 31;
    if (warp >= Nn) return;
    int n = warp;
    const float* __restrict__ hin = hbuf(insel);
    int h = *hptr;
    float relv = g_rel[layer * Dd + lane];

    float b = (n == h) ? 0.0f : 100.0f;
    float sum = b, sq = b * b, mx = b, mn = b;
    float bestS = 32.0f * b;
    int bestSrc = n;

    int st = g_start[n];
    int cnt = g_indeg[n];
    for (int base = 0; base < cnt; base += 32) {
        int rem = cnt - base;
        int m = rem < 32 ? rem : 32;
        int2 ed = make_int2(0, 0);
        if (lane < m) ed = g_csr[st + base + lane];

        int j = 0;
        for (; j + 4 <= m; j += 4) {
            int s0 = __shfl_sync(0xffffffffu, ed.x, j + 0);
            int s1 = __shfl_sync(0xffffffffu, ed.x, j + 1);
            int s2 = __shfl_sync(0xffffffffu, ed.x, j + 2);
            int s3 = __shfl_sync(0xffffffffu, ed.x, j + 3);
            float w0 = __int_as_float(__shfl_sync(0xffffffffu, ed.y, j + 0));
            float w1 = __int_as_float(__shfl_sync(0xffffffffu, ed.y, j + 1));
            float w2 = __int_as_float(__shfl_sync(0xffffffffu, ed.y, j + 2));
            float w3 = __int_as_float(__shfl_sync(0xffffffffu, ed.y, j + 3));
            // issue all gathers before accumulating (MLP=4)
            float v0 = hin[s0 * Dd + lane];
            float v1 = hin[s1 * Dd + lane];
            float v2 = hin[s2 * Dd + lane];
            float v3 = hin[s3 * Dd + lane];
            float D0 = 0.f, D1 = 0.f, D2 = 0.f, D3 = 0.f;
            if (LAST) { D0 = g_D[s0]; D1 = g_D[s1]; D2 = g_D[s2]; D3 = g_D[s3]; }

            float m0 = v0 * relv, wm0 = m0 * w0;
            sum += wm0; sq += m0 * m0 * w0;
            mx = fmaxf(mx, wm0); mn = fminf(mn, wm0);
            float m1 = v1 * relv, wm1 = m1 * w1;
            sum += wm1; sq += m1 * m1 * w1;
            mx = fmaxf(mx, wm1); mn = fminf(mn, wm1);
            float m2 = v2 * relv, wm2 = m2 * w2;
            sum += wm2; sq += m2 * m2 * w2;
            mx = fmaxf(mx, wm2); mn = fminf(mn, wm2);
            float m3 = v3 * relv, wm3 = m3 * w3;
            sum += wm3; sq += m3 * m3 * w3;
            mx = fmaxf(mx, wm3); mn = fminf(mn, wm3);

            if (LAST) {
                float sc0 = w0 * D0, sc1 = w1 * D1, sc2 = w2 * D2, sc3 = w3 * D3;
                if (sc0 > bestS) { bestS = sc0; bestSrc = s0; }
                else if (sc0 == bestS) bestSrc = min(bestSrc, s0);
                if (sc1 > bestS) { bestS = sc1; bestSrc = s1; }
                else if (sc1 == bestS) bestSrc = min(bestSrc, s1);
                if (sc2 > bestS) { bestS = sc2; bestSrc = s2; }
                else if (sc2 == bestS) bestSrc = min(bestSrc, s2);
                if (sc3 > bestS) { bestS = sc3; bestSrc = s3; }
                else if (sc3 == bestS) bestSrc = min(bestSrc, s3);
            }
        }
        for (; j < m; j++) {
            int s0 = __shfl_sync(0xffffffffu, ed.x, j);
            float w0 = __int_as_float(__shfl_sync(0xffffffffu, ed.y, j));
            float m0 = hin[s0 * Dd + lane] * relv;
            float wm0 = m0 * w0;
            sum += wm0; sq += m0 * m0 * w0;
            mx = fmaxf(mx, wm0); mn = fminf(mn, wm0);
            if (LAST) {
                float sc = w0 * g_D[s0];
                if (sc > bestS) { bestS = sc; bestSrc = s0; }
                else if (sc == bestS) bestSrc = min(bestSrc, s0);
            }
        }
    }
    float c = (float)(cnt + 1);
    float mean = sum / c;
    float sqm = sq / c;
    float sd = sqrtf(fmaxf(sqm - mean * mean, 1e-6f));

    // write split-bf16 GEMM row: [h(32) | feats(128)]
    float hv = hin[n * Dd + lane];
    __nv_bfloat16 hh = __float2bfloat16_rn(hv);
    g_Xh[n * KK + lane] = hh;
    g_Xl[n * KK + lane] = __float2bfloat16_rn(hv - __bfloat162float(hh));

    union { __nv_bfloat16 v[4]; uint2 u; } ph, pl;
    float fv[4] = {mean, mx, mn, sd};
    #pragma unroll
    for (int t = 0; t < 4; t++) {
        __nv_bfloat16 fh = __float2bfloat16_rn(fv[t]);
        ph.v[t] = fh;
        pl.v[t] = __float2bfloat16_rn(fv[t] - __bfloat162float(fh));
    }
    *reinterpret_cast<uint2*>(&g_Xh[n * KK + Dd + lane * 4]) = ph.u;
    *reinterpret_cast<uint2*>(&g_Xl[n * KK + Dd + lane * 4]) = pl.u;

    if (LAST && lane == 0) g_pred[n] = bestSrc;
}

// ---------------- tensor-core GEMM + fused epilogue (+optional dot for layer NL-2)
template <int DOT>
__global__ void k_gemm(const float* __restrict__ linb, int layer, int outsel) {
    extern __shared__ char sm_[];
    __nv_bfloat16* Bh = reinterpret_cast<__nv_bfloat16*>(sm_);
    __nv_bfloat16* Bl = Bh + KK * B_LD;
    __nv_bfloat16* Ah = Bl + KK * B_LD;
    __nv_bfloat16* Al = Ah + BM * A_LD;
    float* Cs = reinterpret_cast<float*>(sm_);

    float* __restrict__ hout = hbuf(outsel);
    int row0 = blockIdx.x * BM;
    int wid = threadIdx.x >> 5;
    int lane = threadIdx.x & 31;

    {
        const uint4* srcH = reinterpret_cast<const uint4*>(g_Wbh + layer * KK * CN);
        const uint4* srcL = reinterpret_cast<const uint4*>(g_Wbl + layer * KK * CN);
        for (int i = threadIdx.x; i < KK * CN / 8; i += 256) {
            int r = i / 12, c = i % 12;
            reinterpret_cast<uint4*>(Bh + r * B_LD)[c] = srcH[i];
            reinterpret_cast<uint4*>(Bl + r * B_LD)[c] = srcL[i];
        }
    }

    wmma::fragment<wmma::accumulator, 16, 16, 16, float> acc[6];
    #pragma unroll
    for (int t = 0; t < 6; t++) wmma::fill_fragment(acc[t], 0.0f);

    for (int kt = 0; kt < KK; kt += 32) {
        __syncthreads();
        for (int i = threadIdx.x; i < BM * 32 / 8; i += 256) {
            int r = i >> 2, c = i & 3;
            size_t goff = (size_t)(row0 + r) * KK + kt + c * 8;
            reinterpret_cast<uint4*>(Ah + r * A_LD)[c] =
                *reinterpret_cast<const uint4*>(g_Xh + goff);
            reinterpret_cast<uint4*>(Al + r * A_LD)[c] =
                *reinterpret_cast<const uint4*>(g_Xl + goff);
        }
        __syncthreads();

        #pragma unroll
        for (int ks = 0; ks < 32; ks += 16) {
            wmma::fragment<wmma::matrix_a, 16, 16, 16, __nv_bfloat16, wmma::row_major> ah, al;
            wmma::load_matrix_sync(ah, Ah + wid * 16 * A_LD + ks, A_LD);
            wmma::load_matrix_sync(al, Al + wid * 16 * A_LD + ks, A_LD);
            #pragma unroll
            for (int t = 0; t < 6; t++) {
                wmma::fragment<wmma::matrix_b, 16, 16, 16, __nv_bfloat16, wmma::row_major> bh, bl;
                wmma::load_matrix_sync(bh, Bh + (kt + ks) * B_LD + t * 16, B_LD);
                wmma::load_matrix_sync(bl, Bl + (kt + ks) * B_LD + t * 16, B_LD);
                wmma::mma_sync(acc[t], ah, bh, acc[t]);
                wmma::mma_sync(acc[t], ah, bl, acc[t]);
                wmma::mma_sync(acc[t], al, bh, acc[t]);
            }
        }
    }

    __syncthreads();
    #pragma unroll
    for (int t = 0; t < 6; t++)
        wmma::store_matrix_sync(Cs + wid * 16 * CN + t * 16, acc[t], CN, wmma::mem_row_major);
    __syncthreads();

    float relD = 0.0f;
    if (DOT) relD = g_rel[(NL - 1) * Dd + lane];   // lane == d in epilogue loop

    for (int i = threadIdx.x; i < BM * Dd; i += 256) {
        int r = i >> 5, d = i & 31;   // d == lane (stride 256 preserves low 5 bits)
        int n = row0 + r;
        float v = 0.0f;
        bool ok = (n < Nn);
        if (ok) {
            float s = g_scale[n];
            float inv = 1.0f / fmaxf(s, 0.01f);
            v = Cs[r * CN + d] + s * Cs[r * CN + 32 + d] + inv * Cs[r * CN + 64 + d]
                + linb[layer * Dd + d];
            v = fmaxf(v, 0.0f);
            hout[n * Dd + d] = v;
        }
        if (DOT) {
            float dv = v * relD;
            #pragma unroll
            for (int o = 16; o; o >>= 1) dv += __shfl_xor_sync(0xffffffffu, dv, o);
            if (ok && lane == 0) g_D[n] = dv;
        }
    }
}

// ---------------- final MLP + output assembly ----------------
__global__ void k_final(int insel, const float* __restrict__ q,
                        const float* __restrict__ W1, const float* __restrict__ b1,
                        const float* __restrict__ W2, const float* __restrict__ b2,
                        float* __restrict__ out) {
    __shared__ float sW1[64 * 64];
    __shared__ float sW2[64];
    __shared__ float sb1[64];
    __shared__ float sq[32];
    int tid = threadIdx.x;
    for (int i = tid; i < 4096; i += 256) sW1[i] = W1[i];
    if (tid < 64) { sW2[tid] = W2[tid]; sb1[tid] = b1[tid]; }
    if (tid < 32) sq[tid] = q[tid];
    __syncthreads();

    const float* __restrict__ hfin = hbuf(insel);
    int warp = (blockIdx.x * blockDim.x + tid) >> 5;
    int lane = tid & 31;
    if (warp >= Nn) return;
    int n = warp;
    float hv = hfin[n * Dd + lane];
    float a0 = sb1[lane], a1 = sb1[lane + 32];
    #pragma unroll
    for (int k = 0; k < 32; k++) {
        float xv = __shfl_sync(0xffffffffu, hv, k);
        a0 += xv * sW1[k * 64 + lane];
        a1 += xv * sW1[k * 64 + 32 + lane];
    }
    #pragma unroll
    for (int k = 0; k < 32; k++) {
        float xv = sq[k];
        a0 += xv * sW1[(32 + k) * 64 + lane];
        a1 += xv * sW1[(32 + k) * 64 + 32 + lane];
    }
    a0 = fmaxf(a0, 0.0f);
    a1 = fmaxf(a1, 0.0f);
    float p = a0 * sW2[lane] + a1 * sW2[lane + 32];
    #pragma unroll
    for (int o = 16; o; o >>= 1) p += __shfl_xor_sync(0xffffffffu, p, o);
    if (lane == 0) {
        out[n] = p + b2[0];
        out[Nn + n] = (float)g_pred[n];
    }
}

// ---------------- launch ----------------
extern "C" void kernel_launch(void* const* d_in, const int* in_sizes, int n_in,
                              void* d_out, int out_size) {
    const int*   node_in  = (const int*)d_in[0];
    const int*   node_out = (const int*)d_in[1];
    const float* ew       = (const float*)d_in[2];
    const int*   hptr     = (const int*)d_in[3];
    const float* qw       = (const float*)d_in[4];
    const float* relW     = (const float*)d_in[5];
    const float* relb     = (const float*)d_in[6];
    const float* linW     = (const float*)d_in[7];
    const float* linb     = (const float*)d_in[8];
    const float* W1       = (const float*)d_in[9];
    const float* b1       = (const float*)d_in[10];
    const float* W2       = (const float*)d_in[11];
    const float* b2       = (const float*)d_in[12];
    float* out = (float*)d_out;

    static bool attr_set = false;
    if (!attr_set) {
        cudaFuncSetAttribute(k_gemm<0>, cudaFuncAttributeMaxDynamicSharedMemorySize, GEMM_SMEM);
        cudaFuncSetAttribute(k_gemm<1>, cudaFuncAttributeMaxDynamicSharedMemorySize, GEMM_SMEM);
        attr_set = true;
    }

    k_init<<<(Nn * Dd + 255) / 256, 256>>>(hptr, qw, relW, relb, linW);
    k_count<<<(Ee + 255) / 256, 256>>>(node_out, ew);
    k_alloc<<<(Nn + 255) / 256, 256>>>();
    k_scatter<<<(Ee + 255) / 256, 256>>>(node_out, node_in, ew);

    int cur = 0;
    for (int l = 0; l < NL; l++) {
        if (l == NL - 1) k_agg<1><<<(Nn + 7) / 8, 256>>>(hptr, cur, l);
        else             k_agg<0><<<(Nn + 7) / 8, 256>>>(hptr, cur, l);
        if (l == NL - 2) k_gemm<1><<<(NR / BM), 256, GEMM_SMEM>>>(linb, l, cur ^ 1);
        else             k_gemm<0><<<(NR / BM), 256, GEMM_SMEM>>>(linb, l, cur ^ 1);
        cur ^= 1;
    }
    k_final<<<(Nn + 7) / 8, 256>>>(cur, qw, W1, b1, W2, b2, out);
}

// round 8
// speedup vs baseline: 1.1269x; 1.0060x over previous
#include <cuda_runtime.h>
#include <cuda_bf16.h>
#include <mma.h>
#include <math.h>

using namespace nvcuda;

#define Nn 50000
#define NR 50048
#define Ee 800000
#define Dd 32
#define NL 6
#define KK 160
#define CN 96
#define BM 128
#define A_LD 40
#define B_LD 104
#define GEMM_SMEM ((2*KK*B_LD + 2*BM*A_LD) * 2)

// ---------------- device scratch ----------------
__device__ float g_h0[Nn * Dd];
__device__ float g_h1[Nn * Dd];
__device__ __nv_bfloat16 g_Xh[NR * KK];
__device__ __nv_bfloat16 g_Xl[NR * KK];
__device__ __nv_bfloat16 g_Wbh[NL * KK * CN];
__device__ __nv_bfloat16 g_Wbl[NL * KK * CN];
__device__ float g_scale[Nn];
__device__ float g_deg[Nn];
__device__ int   g_indeg[Nn];
__device__ int   g_start[Nn];
__device__ int   g_cursor[Nn];
__device__ int2  g_csr[Ee];
__device__ float g_rel[NL * Dd];
__device__ float g_D[Nn];
__device__ float g_sum;
__device__ int   g_tot;
__device__ int   g_pred[Nn];

__device__ __forceinline__ float* hbuf(int s) { return s ? g_h1 : g_h0; }

// ---------------- seed: counters must be initialized BEFORE any atomic accum ---
__global__ void k_seed() {
    int idx = blockIdx.x * blockDim.x + threadIdx.x;
    if (idx < Nn) {
        g_deg[idx] = 1.0f;
        g_indeg[idx] = 0;
    }
    if (idx == 0) { g_sum = 0.0f; g_tot = 0; }
}

// ------- init + edge count fused: boundary, rel, Wc build, degree atomics ------
// NOTE: g_deg/g_indeg are seeded in k_seed (previous launch). This kernel only
// accumulates into them — no seeding here (cross-block race otherwise).
__global__ void k_init(const int* __restrict__ hptr, const float* __restrict__ q,
                       const float* __restrict__ relW, const float* __restrict__ relb,
                       const float* __restrict__ linW,
                       const int* __restrict__ node_out, const float* __restrict__ ew) {
    int idx = blockIdx.x * blockDim.x + threadIdx.x;
    if (idx < Nn * Dd) {
        int n = idx >> 5;
        int h = *hptr;
        g_h0[idx] = (n == h) ? 0.0f : 100.0f;
    }
    if (idx < NL * KK * CN) {
        int l = idx / (KK * CN);
        int rem = idx % (KK * CN);
        int k = rem / CN;
        int j = rem % CN;
        float v;
        if (k < 32) {
            v = (j < 32) ? linW[(l * 416 + k) * 32 + j] : 0.0f;
        } else {
            int f = k - 32, g = j >> 5, d = j & 31;
            v = linW[(l * 416 + 32 + f * 3 + g) * 32 + d];
        }
        __nv_bfloat16 hh = __float2bfloat16_rn(v);
        g_Wbh[idx] = hh;
        g_Wbl[idx] = __float2bfloat16_rn(v - __bfloat162float(hh));
    }
    if (idx < NL * Dd) {
        int i = idx >> 5, d = idx & 31;
        float acc = relb[i * Dd + d];
        for (int k = 0; k < Dd; k++)
            acc += q[k] * relW[(i * Dd + k) * Dd + d];
        g_rel[i * Dd + d] = acc;
    }
    if (idx < Ee) {
        int o = node_out[idx];
        atomicAdd(&g_deg[o], ew[idx]);
        atomicAdd(&g_indeg[o], 1);
    }
}

// ---------------- segment allocation + log(deg) partial sum ----------------
__global__ void k_alloc() {
    int i = blockIdx.x * blockDim.x + threadIdx.x;
    float s = 0.0f;
    if (i < Nn) {
        int c = g_indeg[i];
        int st = atomicAdd(&g_tot, c);
        g_start[i] = st;
        g_cursor[i] = st;
        s = logf(g_deg[i]);
        g_scale[i] = s;
    }
    for (int o = 16; o; o >>= 1) s += __shfl_xor_sync(0xffffffffu, s, o);
    __shared__ float wsum[8];
    int lane = threadIdx.x & 31, wid = threadIdx.x >> 5;
    if (lane == 0) wsum[wid] = s;
    __syncthreads();
    if (threadIdx.x == 0) {
        float t = 0.0f;
        for (int w = 0; w < 8; w++) t += wsum[w];
        atomicAdd(&g_sum, t);
    }
}

// ---------------- CSR scatter + scale normalize ----------------
__global__ void k_scatter(const int* __restrict__ node_out, const int* __restrict__ node_in,
                          const float* __restrict__ ew) {
    int e = blockIdx.x * blockDim.x + threadIdx.x;
    if (e < Nn) g_scale[e] = g_scale[e] * ((float)Nn / g_sum);
    if (e >= Ee) return;
    int n = node_out[e];
    int p = atomicAdd(&g_cursor[n], 1);
    g_csr[p] = make_int2(node_in[e], __float_as_int(ew[e]));
}

// ---------------- aggregation: warp per node, lane = dim, MLP=4 (champion body)
template <int LAST>
__global__ void k_agg(const int* __restrict__ hptr, int insel, int layer) {
    int warp = (blockIdx.x * blockDim.x + threadIdx.x) >> 5;
    int lane = threadIdx.x & 31;
    if (warp >= Nn) return;
    int n = warp;
    const float* __restrict__ hin = hbuf(insel);
    int h = *hptr;
    float relv = g_rel[layer * Dd + lane];

    float b = (n == h) ? 0.0f : 100.0f;
    float sum = b, sq = b * b, mx = b, mn = b;
    float bestS = 32.0f * b;
    int bestSrc = n;

    int st = g_start[n];
    int cnt = g_indeg[n];
    for (int base = 0; base < cnt; base += 32) {
        int rem = cnt - base;
        int m = rem < 32 ? rem : 32;
        int2 ed = make_int2(0, 0);
        if (lane < m) ed = g_csr[st + base + lane];

        int j = 0;
        for (; j + 4 <= m; j += 4) {
            int s0 = __shfl_sync(0xffffffffu, ed.x, j + 0);
            int s1 = __shfl_sync(0xffffffffu, ed.x, j + 1);
            int s2 = __shfl_sync(0xffffffffu, ed.x, j + 2);
            int s3 = __shfl_sync(0xffffffffu, ed.x, j + 3);
            float w0 = __int_as_float(__shfl_sync(0xffffffffu, ed.y, j + 0));
            float w1 = __int_as_float(__shfl_sync(0xffffffffu, ed.y, j + 1));
            float w2 = __int_as_float(__shfl_sync(0xffffffffu, ed.y, j + 2));
            float w3 = __int_as_float(__shfl_sync(0xffffffffu, ed.y, j + 3));
            // issue all gathers before accumulating (MLP=4)
            float v0 = hin[s0 * Dd + lane];
            float v1 = hin[s1 * Dd + lane];
            float v2 = hin[s2 * Dd + lane];
            float v3 = hin[s3 * Dd + lane];
            float D0 = 0.f, D1 = 0.f, D2 = 0.f, D3 = 0.f;
            if (LAST) { D0 = g_D[s0]; D1 = g_D[s1]; D2 = g_D[s2]; D3 = g_D[s3]; }

            float m0 = v0 * relv, wm0 = m0 * w0;
            sum += wm0; sq += m0 * m0 * w0;
            mx = fmaxf(mx, wm0); mn = fminf(mn, wm0);
            float m1 = v1 * relv, wm1 = m1 * w1;
            sum += wm1; sq += m1 * m1 * w1;
            mx = fmaxf(mx, wm1); mn = fminf(mn, wm1);
            float m2 = v2 * relv, wm2 = m2 * w2;
            sum += wm2; sq += m2 * m2 * w2;
            mx = fmaxf(mx, wm2); mn = fminf(mn, wm2);
            float m3 = v3 * relv, wm3 = m3 * w3;
            sum += wm3; sq += m3 * m3 * w3;
            mx = fmaxf(mx, wm3); mn = fminf(mn, wm3);

            if (LAST) {
                float sc0 = w0 * D0, sc1 = w1 * D1, sc2 = w2 * D2, sc3 = w3 * D3;
                if (sc0 > bestS) { bestS = sc0; bestSrc = s0; }
                else if (sc0 == bestS) bestSrc = min(bestSrc, s0);
                if (sc1 > bestS) { bestS = sc1; bestSrc = s1; }
                else if (sc1 == bestS) bestSrc = min(bestSrc, s1);
                if (sc2 > bestS) { bestS = sc2; bestSrc = s2; }
                else if (sc2 == bestS) bestSrc = min(bestSrc, s2);
                if (sc3 > bestS) { bestS = sc3; bestSrc = s3; }
                else if (sc3 == bestS) bestSrc = min(bestSrc, s3);
            }
        }
        for (; j < m; j++) {
            int s0 = __shfl_sync(0xffffffffu, ed.x, j);
            float w0 = __int_as_float(__shfl_sync(0xffffffffu, ed.y, j));
            float m0 = hin[s0 * Dd + lane] * relv;
            float wm0 = m0 * w0;
            sum += wm0; sq += m0 * m0 * w0;
            mx = fmaxf(mx, wm0); mn = fminf(mn, wm0);
            if (LAST) {
                float sc = w0 * g_D[s0];
                if (sc > bestS) { bestS = sc; bestSrc = s0; }
                else if (sc == bestS) bestSrc = min(bestSrc, s0);
            }
        }
    }
    float c = (float)(cnt + 1);
    float mean = sum / c;
    float sqm = sq / c;
    float sd = sqrtf(fmaxf(sqm - mean * mean, 1e-6f));

    // write split-bf16 GEMM row: [h(32) | feats(128)]
    float hv = hin[n * Dd + lane];
    __nv_bfloat16 hh = __float2bfloat16_rn(hv);
    g_Xh[n * KK + lane] = hh;
    g_Xl[n * KK + lane] = __float2bfloat16_rn(hv - __bfloat162float(hh));

    union { __nv_bfloat16 v[4]; uint2 u; } ph, pl;
    float fv[4] = {mean, mx, mn, sd};
    #pragma unroll
    for (int t = 0; t < 4; t++) {
        __nv_bfloat16 fh = __float2bfloat16_rn(fv[t]);
        ph.v[t] = fh;
        pl.v[t] = __float2bfloat16_rn(fv[t] - __bfloat162float(fh));
    }
    *reinterpret_cast<uint2*>(&g_Xh[n * KK + Dd + lane * 4]) = ph.u;
    *reinterpret_cast<uint2*>(&g_Xl[n * KK + Dd + lane * 4]) = pl.u;

    if (LAST && lane == 0) g_pred[n] = bestSrc;
}

// ---------------- tensor-core GEMM + fused epilogue (+optional dot) ----------
template <int DOT>
__global__ void k_gemm(const float* __restrict__ linb, int layer, int outsel) {
    extern __shared__ char sm_[];
    __nv_bfloat16* Bh = reinterpret_cast<__nv_bfloat16*>(sm_);
    __nv_bfloat16* Bl = Bh + KK * B_LD;
    __nv_bfloat16* Ah = Bl + KK * B_LD;
    __nv_bfloat16* Al = Ah + BM * A_LD;
    float* Cs = reinterpret_cast<float*>(sm_);

    float* __restrict__ hout = hbuf(outsel);
    int row0 = blockIdx.x * BM;
    int wid = threadIdx.x >> 5;
    int lane = threadIdx.x & 31;

    {
        const uint4* srcH = reinterpret_cast<const uint4*>(g_Wbh + layer * KK * CN);
        const uint4* srcL = reinterpret_cast<const uint4*>(g_Wbl + layer * KK * CN);
        for (int i = threadIdx.x; i < KK * CN / 8; i += 256) {
            int r = i / 12, c = i % 12;
            reinterpret_cast<uint4*>(Bh + r * B_LD)[c] = srcH[i];
            reinterpret_cast<uint4*>(Bl + r * B_LD)[c] = srcL[i];
        }
    }

    wmma::fragment<wmma::accumulator, 16, 16, 16, float> acc[6];
    #pragma unroll
    for (int t = 0; t < 6; t++) wmma::fill_fragment(acc[t], 0.0f);

    for (int kt = 0; kt < KK; kt += 32) {
        __syncthreads();
        for (int i = threadIdx.x; i < BM * 32 / 8; i += 256) {
            int r = i >> 2, c = i & 3;
            size_t goff = (size_t)(row0 + r) * KK + kt + c * 8;
            reinterpret_cast<uint4*>(Ah + r * A_LD)[c] =
                *reinterpret_cast<const uint4*>(g_Xh + goff);
            reinterpret_cast<uint4*>(Al + r * A_LD)[c] =
                *reinterpret_cast<const uint4*>(g_Xl + goff);
        }
        __syncthreads();

        #pragma unroll
        for (int ks = 0; ks < 32; ks += 16) {
            wmma::fragment<wmma::matrix_a, 16, 16, 16, __nv_bfloat16, wmma::row_major> ah, al;
            wmma::load_matrix_sync(ah, Ah + wid * 16 * A_LD + ks, A_LD);
            wmma::load_matrix_sync(al, Al + wid * 16 * A_LD + ks, A_LD);
            #pragma unroll
            for (int t = 0; t < 6; t++) {
                wmma::fragment<wmma::matrix_b, 16, 16, 16, __nv_bfloat16, wmma::row_major> bh, bl;
                wmma::load_matrix_sync(bh, Bh + (kt + ks) * B_LD + t * 16, B_LD);
                wmma::load_matrix_sync(bl, Bl + (kt + ks) * B_LD + t * 16, B_LD);
                wmma::mma_sync(acc[t], ah, bh, acc[t]);
                wmma::mma_sync(acc[t], ah, bl, acc[t]);
                wmma::mma_sync(acc[t], al, bh, acc[t]);
            }
        }
    }

    __syncthreads();
    #pragma unroll
    for (int t = 0; t < 6; t++)
        wmma::store_matrix_sync(Cs + wid * 16 * CN + t * 16, acc[t], CN, wmma::mem_row_major);
    __syncthreads();

    float relD = 0.0f;
    if (DOT) relD = g_rel[(NL - 1) * Dd + lane];

    for (int i = threadIdx.x; i < BM * Dd; i += 256) {
        int r = i >> 5, d = i & 31;
        int n = row0 + r;
        float v = 0.0f;
        bool ok = (n < Nn);
        if (ok) {
            float s = g_scale[n];
            float inv = 1.0f / fmaxf(s, 0.01f);
            v = Cs[r * CN + d] + s * Cs[r * CN + 32 + d] + inv * Cs[r * CN + 64 + d]
                + linb[layer * Dd + d];
            v = fmaxf(v, 0.0f);
            hout[n * Dd + d] = v;
        }
        if (DOT) {
            float dv = v * relD;
            #pragma unroll
            for (int o = 16; o; o >>= 1) dv += __shfl_xor_sync(0xffffffffu, dv, o);
            if (ok && lane == 0) g_D[n] = dv;
        }
    }
}

// ---------------- final MLP + output assembly ----------------
__global__ void k_final(int insel, const float* __restrict__ q,
                        const float* __restrict__ W1, const float* __restrict__ b1,
                        const float* __restrict__ W2, const float* __restrict__ b2,
                        float* __restrict__ out) {
    __shared__ float sW1[64 * 64];
    __shared__ float sW2[64];
    __shared__ float sb1[64];
    __shared__ float sq[32];
    int tid = threadIdx.x;
    for (int i = tid; i < 4096; i += 256) sW1[i] = W1[i];
    if (tid < 64) { sW2[tid] = W2[tid]; sb1[tid] = b1[tid]; }
    if (tid < 32) sq[tid] = q[tid];
    __syncthreads();

    const float* __restrict__ hfin = hbuf(insel);
    int warp = (blockIdx.x * blockDim.x + tid) >> 5;
    int lane = tid & 31;
    if (warp >= Nn) return;
    int n = warp;
    float hv = hfin[n * Dd + lane];
    float a0 = sb1[lane], a1 = sb1[lane + 32];
    #pragma unroll
    for (int k = 0; k < 32; k++) {
        float xv = __shfl_sync(0xffffffffu, hv, k);
        a0 += xv * sW1[k * 64 + lane];
        a1 += xv * sW1[k * 64 + 32 + lane];
    }
    #pragma unroll
    for (int k = 0; k < 32; k++) {
        float xv = sq[k];
        a0 += xv * sW1[(32 + k) * 64 + lane];
        a1 += xv * sW1[(32 + k) * 64 + 32 + lane];
    }
    a0 = fmaxf(a0, 0.0f);
    a1 = fmaxf(a1, 0.0f);
    float p = a0 * sW2[lane] + a1 * sW2[lane + 32];
    #pragma unroll
    for (int o = 16; o; o >>= 1) p += __shfl_xor_sync(0xffffffffu, p, o);
    if (lane == 0) {
        out[n] = p + b2[0];
        out[Nn + n] = (float)g_pred[n];
    }
}

// ---------------- launch ----------------
extern "C" void kernel_launch(void* const* d_in, const int* in_sizes, int n_in,
                              void* d_out, int out_size) {
    const int*   node_in  = (const int*)d_in[0];
    const int*   node_out = (const int*)d_in[1];
    const float* ew       = (const float*)d_in[2];
    const int*   hptr     = (const int*)d_in[3];
    const float* qw       = (const float*)d_in[4];
    const float* relW     = (const float*)d_in[5];
    const float* relb     = (const float*)d_in[6];
    const float* linW     = (const float*)d_in[7];
    const float* linb     = (const float*)d_in[8];
    const float* W1       = (const float*)d_in[9];
    const float* b1       = (const float*)d_in[10];
    const float* W2       = (const float*)d_in[11];
    const float* b2       = (const float*)d_in[12];
    float* out = (float*)d_out;

    static bool attr_set = false;
    if (!attr_set) {
        cudaFuncSetAttribute(k_gemm<0>, cudaFuncAttributeMaxDynamicSharedMemorySize, GEMM_SMEM);
        cudaFuncSetAttribute(k_gemm<1>, cudaFuncAttributeMaxDynamicSharedMemorySize, GEMM_SMEM);
        attr_set = true;
    }

    k_seed<<<(Nn + 255) / 256, 256>>>();
    k_init<<<(Ee + 255) / 256, 256>>>(hptr, qw, relW, relb, linW, node_out, ew);
    k_alloc<<<(Nn + 255) / 256, 256>>>();
    k_scatter<<<(Ee + 255) / 256, 256>>>(node_out, node_in, ew);

    int cur = 0;
    for (int l = 0; l < NL; l++) {
        if (l == NL - 1) k_agg<1><<<(Nn + 7) / 8, 256>>>(hptr, cur, l);
        else             k_agg<0><<<(Nn + 7) / 8, 256>>>(hptr, cur, l);
        if (l == NL - 2) k_gemm<1><<<(NR / BM), 256, GEMM_SMEM>>>(linb, l, cur ^ 1);
        else             k_gemm<0><<<(NR / BM), 256, GEMM_SMEM>>>(linb, l, cur ^ 1);
        cur ^= 1;
    }
    k_final<<<(Nn + 7) / 8, 256>>>(cur, qw, W1, b1, W2, b2, out);
}